// round 7
// baseline (speedup 1.0000x reference)
#include <cuda_runtime.h>

#define NB   256   // batch
#define HD   1024  // hidden
#define NOBS 256   // obs dim
#define NA   18    // actions
#define SPLIT 4

// Scratch (allocation-free rule: __device__ globals). Ping-pong partial buffers.
__device__ float g_pA[SPLIT * NB * HD];
__device__ float g_pB[SPLIT * NB * HD];

enum { M_FMA = 0, M_MAX = 1, M_MIN = 2 };          // reduction semiring
enum { C_NONE = 0, C_SUM_BIAS = 1, C_MAX = 2 };    // inline combine of producer's split-K partials

constexpr int BT = 32;       // batch tile
constexpr int OT = 128;      // out tile
constexpr int KC = 64;       // k chunk (64: halves __syncthreads count vs 32)
constexpr int NT = 256;      // threads
constexpr int WST = OT + 4;  // padded smem strides (kill STS bank conflicts)
constexpr int HST = BT + 4;

// Load h[b, iabs..iabs+3], combining the producer's SPLIT partial slices inline.
template<int COMB>
__device__ __forceinline__ float4 load_h4(const float* __restrict__ hb,
                                          const float* __restrict__ bias, int iabs)
{
    float4 v = *(const float4*)hb;
    if (COMB != C_NONE) {
#pragma unroll
        for (int s = 1; s < SPLIT; s++) {
            const float4 u = *(const float4*)(hb + s * (NB * HD));
            if (COMB == C_SUM_BIAS) {
                v.x += u.x; v.y += u.y; v.z += u.z; v.w += u.w;
            } else {
                v.x = fmaxf(v.x, u.x); v.y = fmaxf(v.y, u.y);
                v.z = fmaxf(v.z, u.z); v.w = fmaxf(v.w, u.w);
            }
        }
        if (COMB == C_SUM_BIAS) {
            const float4 b = *(const float4*)(bias + iabs);
            v.x += b.x; v.y += b.y; v.z += b.z; v.w += b.w;
        }
    }
    return v;
}

// out[b,o] = red_i op(W[o,i], h[b,i]); split-K partials into part[z][b][o].
// h is materialized on the fly from the producer's partials (COMB).
// Per chunk: each thread loads 2 i4-slots (lo and lo+8) per W row group / h.
template<int MODE, int COMB>
__global__ __launch_bounds__(NT)
void semiring_kernel(const float* __restrict__ Wm,
                     const float* __restrict__ Hin,
                     const float* __restrict__ hbias,
                     float* __restrict__ part,
                     int Kld, int Ki)
{
    __shared__ float sh_w[KC * WST];
    __shared__ float sh_h[KC * HST];

    const int tid = threadIdx.x;
    const int o0  = blockIdx.x * OT;
    const int b0  = blockIdx.y * BT;
    const int i0  = blockIdx.z * Ki;

    const int og = tid & 31;   // o4-group: o = o0 + og*4 + oo
    const int bg = tid >> 5;   // b4-group: b = b0 + bg*4 + bb
    const int lo = tid & 7;    // i4 slot for loads (covers i-local via 2 sub-slots)
    const int ro = tid >> 3;   // row slot for loads (0..31)

    const float init = (MODE == M_FMA) ? 0.0f
                     : (MODE == M_MAX) ? -3.402823466e38f : 3.402823466e38f;
    float acc[4][4];
#pragma unroll
    for (int bb = 0; bb < 4; bb++)
#pragma unroll
        for (int oo = 0; oo < 4; oo++) acc[bb][oo] = init;

    const float* wbase = Wm  + (o0 + ro) * Kld + i0 + lo * 4;
    const float* hbase = Hin + (b0 + ro) * Kld + i0 + lo * 4;

    float4 wreg[2][4];
    float4 hreg[2];
    const int nC = Ki / KC;

    // prologue: chunk 0 into regs (two 32-wide halves: s*32 offset in i)
#pragma unroll
    for (int s = 0; s < 2; s++) {
#pragma unroll
        for (int r = 0; r < 4; r++)
            wreg[s][r] = *(const float4*)(wbase + r * 32 * Kld + s * 32);
        hreg[s] = load_h4<COMB>(hbase + s * 32, hbias, i0 + s * 32 + lo * 4);
    }

    for (int c = 0; c < nC; c++) {
        // stage regs -> smem, transposed: sh[i_local][col]
#pragma unroll
        for (int s = 0; s < 2; s++) {
            const int ib = s * 32 + lo * 4;
#pragma unroll
            for (int r = 0; r < 4; r++) {
                const int col = r * 32 + ro;
                sh_w[(ib + 0) * WST + col] = wreg[s][r].x;
                sh_w[(ib + 1) * WST + col] = wreg[s][r].y;
                sh_w[(ib + 2) * WST + col] = wreg[s][r].z;
                sh_w[(ib + 3) * WST + col] = wreg[s][r].w;
            }
            sh_h[(ib + 0) * HST + ro] = hreg[s].x;
            sh_h[(ib + 1) * HST + ro] = hreg[s].y;
            sh_h[(ib + 2) * HST + ro] = hreg[s].z;
            sh_h[(ib + 3) * HST + ro] = hreg[s].w;
        }
        __syncthreads();

        // prefetch next chunk (LDG latency overlapped with compute)
        if (c + 1 < nC) {
            const int ic = (c + 1) * KC;
#pragma unroll
            for (int s = 0; s < 2; s++) {
#pragma unroll
                for (int r = 0; r < 4; r++)
                    wreg[s][r] = *(const float4*)(wbase + r * 32 * Kld + ic + s * 32);
                hreg[s] = load_h4<COMB>(hbase + ic + s * 32, hbias,
                                        i0 + ic + s * 32 + lo * 4);
            }
        }

#pragma unroll 4
        for (int i = 0; i < KC; i++) {
            const float4 wv = *(const float4*)&sh_w[i * WST + og * 4]; // conflict-free
            const float4 hv = *(const float4*)&sh_h[i * HST + bg * 4]; // broadcast
            const float w4[4] = {wv.x, wv.y, wv.z, wv.w};
            const float h4[4] = {hv.x, hv.y, hv.z, hv.w};
#pragma unroll
            for (int bb = 0; bb < 4; bb++)
#pragma unroll
                for (int oo = 0; oo < 4; oo++) {
                    if (MODE == M_FMA)
                        acc[bb][oo] = fmaf(w4[oo], h4[bb], acc[bb][oo]);
                    else if (MODE == M_MAX)
                        acc[bb][oo] = fmaxf(acc[bb][oo], w4[oo] + h4[bb]);
                    else
                        acc[bb][oo] = fminf(acc[bb][oo], w4[oo] + h4[bb]);
                }
        }
        __syncthreads();
    }

    float* pout = part + (blockIdx.z * NB + b0 + bg * 4) * HD + o0 + og * 4;
#pragma unroll
    for (int bb = 0; bb < 4; bb++) {
        const float4 v = make_float4(acc[bb][0], acc[bb][1], acc[bb][2], acc[bb][3]);
        *(float4*)(pout + bb * HD) = v;
    }
}

// q[b,a] = (min-combine of SPLIT partials of h3)[b,:] . W_out[a,:] + b_out[a]
// One warp per output element; inline min-combine of the producer partials.
__global__ __launch_bounds__(256)
void fcout_kernel(const float* __restrict__ hpart, const float* __restrict__ Wout,
                  const float* __restrict__ bout, float* __restrict__ q)
{
    const int wid  = (blockIdx.x * blockDim.x + threadIdx.x) >> 5;
    const int lane = threadIdx.x & 31;
    if (wid >= NB * NA) return;
    const int b = wid / NA;
    const int a = wid % NA;
    const float* hr = hpart + b * HD;
    const float* wr = Wout + a * HD;
    float s = 0.0f;
#pragma unroll
    for (int k = 0; k < HD / 32; k++) {
        const int i = lane + k * 32;
        float h = hr[i];
#pragma unroll
        for (int z = 1; z < SPLIT; z++)
            h = fminf(h, hr[i + z * (NB * HD)]);
        s = fmaf(h, wr[i], s);
    }
#pragma unroll
    for (int d = 16; d; d >>= 1) s += __shfl_xor_sync(0xffffffffu, s, d);
    if (lane == 0) q[b * NA + a] = s + bout[a];
}

extern "C" void kernel_launch(void* const* d_in, const int* in_sizes, int n_in,
                              void* d_out, int out_size)
{
    const float* x     = (const float*)d_in[0];
    const float* W_in  = (const float*)d_in[1];
    const float* b_in  = (const float*)d_in[2];
    const float* W_max = (const float*)d_in[3];
    const float* W_min = (const float*)d_in[4];
    const float* W_out = (const float*)d_in[5];
    const float* b_out = (const float*)d_in[6];
    float* q = (float*)d_out;

    float *pA, *pB;
    cudaGetSymbolAddress((void**)&pA, g_pA);
    cudaGetSymbolAddress((void**)&pB, g_pB);

    const dim3 grid(HD / OT, NB / BT, SPLIT);  // (8, 8, 4) = 256 CTAs

    // 1) fc_in partials: pA[z] = x @ W_in^T (split over obs dim)
    semiring_kernel<M_FMA, C_NONE><<<grid, NT>>>(W_in, x, nullptr, pA, NOBS, NOBS / SPLIT);

    // 2) max-plus: h1 = sum_z pA + b_in materialized inline; pB[z] = partial max-plus
    semiring_kernel<M_MAX, C_SUM_BIAS><<<grid, NT>>>(W_max, pA, b_in, pB, HD, HD / SPLIT);

    // 3) min-plus: h2 = max_z pB inline; pA[z] = partial min-plus
    semiring_kernel<M_MIN, C_MAX><<<grid, NT>>>(W_min, pB, nullptr, pA, HD, HD / SPLIT);

    // 4) fc_out: h3 = min_z pA inline; q = h3 @ W_out^T + b_out
    fcout_kernel<<<(NB * NA * 32) / 256, 256>>>(pA, W_out, b_out, q);
}